// round 11
// baseline (speedup 1.0000x reference)
#include <cuda_runtime.h>
#include <math.h>

#define BATCH 4
#define SEQ 2048
#define DMODEL 768
#define NHEAD 12
#define HDIM 64
#define M_ROWS (BATCH*SEQ)   // 8192

// Scratch (device globals: allocation is forbidden)
__device__ float g_q[(size_t)BATCH*NHEAD*SEQ*HDIM];
__device__ float g_k[(size_t)BATCH*NHEAD*SEQ*HDIM];
__device__ float g_v[(size_t)BATCH*NHEAD*SEQ*HDIM];
__device__ float g_attn[(size_t)M_ROWS*DMODEL];

// ---------------------------------------------------------------------------
// GEMM: C[m,n] = sum_k A[m,k]*W[n,k] + bias[n]   (torch Linear: x @ W^T + b)
// BM=BN=64, BK=16, 256 threads, 4x4 outputs/thread.
// MODE 0: A = host-passed input x; scatter into [b,h,s,hd] (sel picks q/k/v)
// MODE 1: A = g_attn (resolved IN DEVICE CODE — a __device__ symbol passed
//         from host decays to the host shadow address, which on GB300's
//         ATS-coherent C2C silently reads zeros instead of faulting);
//         row-major [m, DMODEL] into Cq.
// ---------------------------------------------------------------------------
template<int MODE>
__global__ void __launch_bounds__(256) gemm_kernel(const float* __restrict__ A,
                                                   const float* __restrict__ W,
                                                   const float* __restrict__ bias,
                                                   float* __restrict__ Cq, int sel)
{
    __shared__ __align__(16) float As[16][68];
    __shared__ __align__(16) float Bs[16][68];
    const int tid = threadIdx.x;
    const int tx = tid & 15, ty = tid >> 4;
    const int m0 = blockIdx.y * 64, n0 = blockIdx.x * 64;
    const int lr = tid >> 2, lc = (tid & 3) * 4;

    const float* Asrc = (MODE == 1) ? (const float*)g_attn : A;

    float acc[4][4] = {};
    const float* Ap = Asrc + (size_t)(m0 + lr) * DMODEL + lc;
    const float* Wp = W    + (size_t)(n0 + lr) * DMODEL + lc;

    for (int k0 = 0; k0 < DMODEL; k0 += 16) {
        float4 av = *(const float4*)(Ap + k0);
        float4 wv = *(const float4*)(Wp + k0);
        __syncthreads();
        As[lc+0][lr]=av.x; As[lc+1][lr]=av.y; As[lc+2][lr]=av.z; As[lc+3][lr]=av.w;
        Bs[lc+0][lr]=wv.x; Bs[lc+1][lr]=wv.y; Bs[lc+2][lr]=wv.z; Bs[lc+3][lr]=wv.w;
        __syncthreads();
        #pragma unroll
        for (int kk = 0; kk < 16; kk++) {
            float4 a = *(const float4*)&As[kk][ty*4];
            float4 b = *(const float4*)&Bs[kk][tx*4];
            float ar[4] = {a.x, a.y, a.z, a.w};
            float br[4] = {b.x, b.y, b.z, b.w};
            #pragma unroll
            for (int i = 0; i < 4; i++)
                #pragma unroll
                for (int j = 0; j < 4; j++)
                    acc[i][j] += ar[i] * br[j];
        }
    }

    float* out = Cq;
    if (MODE == 0) out = (sel == 0) ? g_q : (sel == 1) ? g_k : g_v;

    #pragma unroll
    for (int i = 0; i < 4; i++) {
        int m = m0 + ty*4 + i;
        #pragma unroll
        for (int j = 0; j < 4; j++) {
            int n = n0 + tx*4 + j;
            float v = acc[i][j] + bias[n];
            if (MODE == 0) {
                int b = m >> 11, s = m & 2047;
                int h = n >> 6,  hd = n & 63;
                out[(((size_t)(b*NHEAD + h))*SEQ + s)*HDIM + hd] = v;
            } else {
                out[(size_t)m*DMODEL + n] = v;
            }
        }
    }
}

// ---------------------------------------------------------------------------
// Flash attention, fp32. grid (SEQ/64, BATCH*NHEAD), 256 threads.
// 4 threads (a quad) per query row; thread owns interleaved key-columns /
// output-dims (cg + 4*idx). P never touches shared memory: the PV product
// fetches each P(row, j) from its quad-mate owner via __shfl_sync.
// ---------------------------------------------------------------------------
__global__ void __launch_bounds__(256) attn_kernel()
{
    __shared__ __align__(16) float Ks[64][68];
    __shared__ __align__(16) float Vs[64][68];

    const int tid  = threadIdx.x;
    const int lane = tid & 31;
    const int bh   = blockIdx.y;
    const int q0   = blockIdx.x * 64;
    const int row  = tid >> 2, cg = tid & 3;
    const int lr   = tid >> 2, lc = (tid & 3) * 16;

    // Q row in registers, pre-scaled by 1/sqrt(64)
    float qreg[64];
    {
        const float4* qp = (const float4*)(g_q + ((size_t)bh*SEQ + q0 + row)*HDIM);
        #pragma unroll
        for (int u = 0; u < 16; u++) {
            float4 v = qp[u];
            qreg[4*u+0] = v.x*0.125f; qreg[4*u+1] = v.y*0.125f;
            qreg[4*u+2] = v.z*0.125f; qreg[4*u+3] = v.w*0.125f;
        }
    }

    float m_i = -INFINITY, l_i = 0.f;
    float acc[16] = {};

    for (int kt = 0; kt < SEQ/64; kt++) {
        const float4* kp = (const float4*)(g_k + ((size_t)bh*SEQ + kt*64 + lr)*HDIM + lc);
        const float4* vp = (const float4*)(g_v + ((size_t)bh*SEQ + kt*64 + lr)*HDIM + lc);
        __syncthreads();   // previous iteration's Ks/Vs readers are done
        #pragma unroll
        for (int u = 0; u < 4; u++) {
            *(float4*)&Ks[lr][lc+4*u] = kp[u];
            *(float4*)&Vs[lr][lc+4*u] = vp[u];
        }
        __syncthreads();   // tile fully visible

        // scores for 16 interleaved key columns
        float s[16];
        #pragma unroll
        for (int jj = 0; jj < 16; jj++) {
            const int col = cg + 4*jj;
            const float4* kr = (const float4*)&Ks[col][0];
            float t = 0.f;
            #pragma unroll
            for (int u = 0; u < 16; u++) {
                float4 kv = kr[u];
                t += qreg[4*u+0]*kv.x + qreg[4*u+1]*kv.y
                   + qreg[4*u+2]*kv.z + qreg[4*u+3]*kv.w;
            }
            s[jj] = t;
        }

        // online softmax (quad reduction: 4 threads per row are lane-adjacent)
        float mt = s[0];
        #pragma unroll
        for (int jj = 1; jj < 16; jj++) mt = fmaxf(mt, s[jj]);
        mt = fmaxf(mt, __shfl_xor_sync(0xffffffffu, mt, 1));
        mt = fmaxf(mt, __shfl_xor_sync(0xffffffffu, mt, 2));
        float mnew  = fmaxf(m_i, mt);
        float scale = __expf(m_i - mnew);   // first tile: exp(-inf)=0
        float lsum = 0.f;
        #pragma unroll
        for (int jj = 0; jj < 16; jj++) {
            float p = __expf(s[jj] - mnew);
            s[jj] = p; lsum += p;
        }
        lsum += __shfl_xor_sync(0xffffffffu, lsum, 1);
        lsum += __shfl_xor_sync(0xffffffffu, lsum, 2);
        l_i = l_i*scale + lsum;
        m_i = mnew;
        #pragma unroll
        for (int dd = 0; dd < 16; dd++) acc[dd] *= scale;

        // O += P * V. P(row, j) lives in the quad-mate with cg == (j&3),
        // register s[j>>2]; fetch it with a warp shuffle (j is compile-time).
        #pragma unroll
        for (int j = 0; j < 64; j++) {
            float p = __shfl_sync(0xffffffffu, s[j >> 2], (lane & ~3) | (j & 3));
            #pragma unroll
            for (int dd = 0; dd < 16; dd++) acc[dd] += p * Vs[j][cg + 4*dd];
        }
    }

    float inv = 1.0f / l_i;
    int b = bh / NHEAD, h = bh % NHEAD;
    float* op = g_attn + ((size_t)(b*SEQ) + q0 + row)*DMODEL + h*HDIM;
    #pragma unroll
    for (int dd = 0; dd < 16; dd++) op[cg + 4*dd] = acc[dd] * inv;
}

// ---------------------------------------------------------------------------
// Inputs confirmed (by the invariance of rel_err under remapping) to be in
// signature order: x, QW_w, QW_b, KW_w, KW_b, VW_w, VW_b, OW_w, OW_b.
// ---------------------------------------------------------------------------
extern "C" void kernel_launch(void* const* d_in, const int* in_sizes, int n_in,
                              void* d_out, int out_size)
{
    const float* x   = (const float*)d_in[0];
    const float* qw  = (const float*)d_in[1];
    const float* qb  = (const float*)d_in[2];
    const float* kw  = (const float*)d_in[3];
    const float* kb  = (const float*)d_in[4];
    const float* vw  = (const float*)d_in[5];
    const float* vb  = (const float*)d_in[6];
    const float* ow  = (const float*)d_in[7];
    const float* ob  = (const float*)d_in[8];
    float* out = (float*)d_out;

    dim3 gg(DMODEL/64, M_ROWS/64);          // (12, 128)
    gemm_kernel<0><<<gg, 256>>>(x, qw, qb, nullptr, 0);
    gemm_kernel<0><<<gg, 256>>>(x, kw, kb, nullptr, 1);
    gemm_kernel<0><<<gg, 256>>>(x, vw, vb, nullptr, 2);

    attn_kernel<<<dim3(SEQ/64, BATCH*NHEAD), 256>>>();

    // NOTE: A operand resolved inside the kernel (MODE 1) — never pass a
    // __device__ symbol from host code.
    gemm_kernel<1><<<gg, 256>>>(nullptr, ow, ob, out, 0);
}

// round 12
// speedup vs baseline: 1.5459x; 1.5459x over previous
#include <cuda_runtime.h>
#include <math.h>

#define BATCH 4
#define SEQ 2048
#define DMODEL 768
#define NHEAD 12
#define HDIM 64
#define M_ROWS (BATCH*SEQ)   // 8192

// Scratch (device globals: allocation is forbidden)
__device__ float g_q[(size_t)BATCH*NHEAD*SEQ*HDIM];
__device__ float g_k[(size_t)BATCH*NHEAD*SEQ*HDIM];
__device__ float g_v[(size_t)BATCH*NHEAD*SEQ*HDIM];
__device__ float g_attn[(size_t)M_ROWS*DMODEL];

// ---------------------------------------------------------------------------
// GEMM: C[m,n] = sum_k A[m,k]*W[n,k] + bias[n]   (torch Linear: x @ W^T + b)
// BM=BN=64, BK=16, 256 threads, 4x4 outputs/thread.
// MODE 0: A = host-passed input x; scatter into [b,h,s,hd] (sel picks q/k/v)
// MODE 1: A = g_attn resolved IN DEVICE CODE (a __device__ symbol passed from
//         host decays to the host shadow; GB300 ATS reads it as zeros).
// ---------------------------------------------------------------------------
template<int MODE>
__global__ void __launch_bounds__(256) gemm_kernel(const float* __restrict__ A,
                                                   const float* __restrict__ W,
                                                   const float* __restrict__ bias,
                                                   float* __restrict__ Cq, int sel)
{
    __shared__ __align__(16) float As[16][68];
    __shared__ __align__(16) float Bs[16][68];
    const int tid = threadIdx.x;
    const int tx = tid & 15, ty = tid >> 4;
    const int m0 = blockIdx.y * 64, n0 = blockIdx.x * 64;
    const int lr = tid >> 2, lc = (tid & 3) * 4;

    const float* Asrc = (MODE == 1) ? (const float*)g_attn : A;

    float acc[4][4] = {};
    const float* Ap = Asrc + (size_t)(m0 + lr) * DMODEL + lc;
    const float* Wp = W    + (size_t)(n0 + lr) * DMODEL + lc;

    for (int k0 = 0; k0 < DMODEL; k0 += 16) {
        float4 av = *(const float4*)(Ap + k0);
        float4 wv = *(const float4*)(Wp + k0);
        __syncthreads();
        As[lc+0][lr]=av.x; As[lc+1][lr]=av.y; As[lc+2][lr]=av.z; As[lc+3][lr]=av.w;
        Bs[lc+0][lr]=wv.x; Bs[lc+1][lr]=wv.y; Bs[lc+2][lr]=wv.z; Bs[lc+3][lr]=wv.w;
        __syncthreads();
        #pragma unroll
        for (int kk = 0; kk < 16; kk++) {
            float4 a = *(const float4*)&As[kk][ty*4];
            float4 b = *(const float4*)&Bs[kk][tx*4];
            float ar[4] = {a.x, a.y, a.z, a.w};
            float br[4] = {b.x, b.y, b.z, b.w};
            #pragma unroll
            for (int i = 0; i < 4; i++)
                #pragma unroll
                for (int j = 0; j < 4; j++)
                    acc[i][j] += ar[i] * br[j];
        }
    }

    float* out = Cq;
    if (MODE == 0) out = (sel == 0) ? g_q : (sel == 1) ? g_k : g_v;

    #pragma unroll
    for (int i = 0; i < 4; i++) {
        int m = m0 + ty*4 + i;
        #pragma unroll
        for (int j = 0; j < 4; j++) {
            int n = n0 + tx*4 + j;
            float v = acc[i][j] + bias[n];
            if (MODE == 0) {
                int b = m >> 11, s = m & 2047;
                int h = n >> 6,  hd = n & 63;
                out[(((size_t)(b*NHEAD + h))*SEQ + s)*HDIM + hd] = v;
            } else {
                out[(size_t)m*DMODEL + n] = v;
            }
        }
    }
}

// ---------------------------------------------------------------------------
// Flash attention, register-blocked GEMM style.
// grid (SEQ/64, BATCH*NHEAD), 256 threads; each thread owns a 4x4 block of
// the 64x64 score tile and of the 64x64 output tile (tx = tid&15 -> key/dim
// columns, ty = tid>>4 -> query rows). Both matmuls are rank-1-update GEMMs
// (2x LDS.128 -> 16 FMA). Q staged in shared once (d-major); K staged d-major
// per tile; P overwrites the K buffer between full block barriers; V read
// row-major. Row softmax reduces over the 16 tx lanes via shfl_xor (lane
// bits 0-3), which never leaves the warp.
// Dynamic shared: Qs[64][68] | KPs[64][68] | Vs[64][68]  (51 KB).
// ---------------------------------------------------------------------------
#define QS(d,m)  sm[(d)*68 + (m)]
#define KS(d,n)  sm[4352 + (d)*68 + (n)]
#define VS(j,e)  sm[8704 + (j)*68 + (e)]
#define ATTN_SMEM (3*64*68*4)

__global__ void __launch_bounds__(256, 2) attn_kernel()
{
    extern __shared__ __align__(16) float sm[];

    const int tid = threadIdx.x;
    const int tx  = tid & 15, ty = tid >> 4;
    const int bh  = blockIdx.y;
    const int q0  = blockIdx.x * 64;
    const int lr  = tid >> 2, lc = (tid & 3) * 16;

    // Stage Q tile once, d-major, pre-scaled by 1/sqrt(64)
    {
        const float4* qp = (const float4*)(g_q + ((size_t)bh*SEQ + q0 + lr)*HDIM + lc);
        #pragma unroll
        for (int u = 0; u < 4; u++) {
            float4 v = qp[u];
            QS(lc+4*u+0, lr) = v.x*0.125f; QS(lc+4*u+1, lr) = v.y*0.125f;
            QS(lc+4*u+2, lr) = v.z*0.125f; QS(lc+4*u+3, lr) = v.w*0.125f;
        }
    }

    float m_i[4], l_i[4], acc[4][4];
    #pragma unroll
    for (int i = 0; i < 4; i++) {
        m_i[i] = -INFINITY; l_i[i] = 0.f;
        #pragma unroll
        for (int j = 0; j < 4; j++) acc[i][j] = 0.f;
    }

    for (int kt = 0; kt < SEQ/64; kt++) {
        const float4* kp = (const float4*)(g_k + ((size_t)bh*SEQ + kt*64 + lr)*HDIM + lc);
        const float4* vp = (const float4*)(g_v + ((size_t)bh*SEQ + kt*64 + lr)*HDIM + lc);
        __syncthreads();                 // prev tile's PV readers done
        #pragma unroll
        for (int u = 0; u < 4; u++) {
            float4 kv = kp[u];
            KS(lc+4*u+0, lr) = kv.x; KS(lc+4*u+1, lr) = kv.y;
            KS(lc+4*u+2, lr) = kv.z; KS(lc+4*u+3, lr) = kv.w;
            *(float4*)&VS(lr, lc+4*u) = vp[u];
        }
        __syncthreads();                 // tiles visible

        // S = Q K^T (4x4 per thread), rank-1 updates over d
        float s[4][4] = {};
        #pragma unroll 16
        for (int d = 0; d < 64; d++) {
            float4 qa = *(const float4*)&QS(d, ty*4);
            float4 kb = *(const float4*)&KS(d, tx*4);
            float qr[4] = {qa.x, qa.y, qa.z, qa.w};
            float kr[4] = {kb.x, kb.y, kb.z, kb.w};
            #pragma unroll
            for (int i = 0; i < 4; i++)
                #pragma unroll
                for (int j = 0; j < 4; j++)
                    s[i][j] += qr[i] * kr[j];
        }

        // online softmax per query row (reduce over 16 tx lanes)
        #pragma unroll
        for (int i = 0; i < 4; i++) {
            float mt = fmaxf(fmaxf(s[i][0], s[i][1]), fmaxf(s[i][2], s[i][3]));
            mt = fmaxf(mt, __shfl_xor_sync(0xffffffffu, mt, 1));
            mt = fmaxf(mt, __shfl_xor_sync(0xffffffffu, mt, 2));
            mt = fmaxf(mt, __shfl_xor_sync(0xffffffffu, mt, 4));
            mt = fmaxf(mt, __shfl_xor_sync(0xffffffffu, mt, 8));
            float mnew  = fmaxf(m_i[i], mt);
            float scale = __expf(m_i[i] - mnew);     // first tile: exp(-inf)=0
            float ls = 0.f;
            #pragma unroll
            for (int j = 0; j < 4; j++) {
                float p = __expf(s[i][j] - mnew);
                s[i][j] = p; ls += p;
            }
            ls += __shfl_xor_sync(0xffffffffu, ls, 1);
            ls += __shfl_xor_sync(0xffffffffu, ls, 2);
            ls += __shfl_xor_sync(0xffffffffu, ls, 4);
            ls += __shfl_xor_sync(0xffffffffu, ls, 8);
            l_i[i] = l_i[i]*scale + ls;
            m_i[i] = mnew;
            #pragma unroll
            for (int j = 0; j < 4; j++) acc[i][j] *= scale;
        }

        __syncthreads();                 // all K reads done -> reuse KS for P^T
        #pragma unroll
        for (int i = 0; i < 4; i++)
            #pragma unroll
            for (int j = 0; j < 4; j++)
                KS(tx*4 + j, ty*4 + i) = s[i][j];    // P^T[j_key][m]
        __syncthreads();                 // P visible

        // O += P V (4x4 per thread), rank-1 updates over key index j
        #pragma unroll 16
        for (int j = 0; j < 64; j++) {
            float4 pa = *(const float4*)&KS(j, ty*4);
            float4 vb = *(const float4*)&VS(j, tx*4);
            float pr[4] = {pa.x, pa.y, pa.z, pa.w};
            float vr[4] = {vb.x, vb.y, vb.z, vb.w};
            #pragma unroll
            for (int i = 0; i < 4; i++)
                #pragma unroll
                for (int jj = 0; jj < 4; jj++)
                    acc[i][jj] += pr[i] * vr[jj];
        }
    }

    const int b = bh / NHEAD, h = bh % NHEAD;
    #pragma unroll
    for (int i = 0; i < 4; i++) {
        float inv = 1.0f / l_i[i];
        float4 o;
        o.x = acc[i][0]*inv; o.y = acc[i][1]*inv;
        o.z = acc[i][2]*inv; o.w = acc[i][3]*inv;
        *(float4*)(g_attn + ((size_t)(b*SEQ) + q0 + ty*4 + i)*DMODEL + h*HDIM + tx*4) = o;
    }
}

// ---------------------------------------------------------------------------
extern "C" void kernel_launch(void* const* d_in, const int* in_sizes, int n_in,
                              void* d_out, int out_size)
{
    const float* x   = (const float*)d_in[0];
    const float* qw  = (const float*)d_in[1];
    const float* qb  = (const float*)d_in[2];
    const float* kw  = (const float*)d_in[3];
    const float* kb  = (const float*)d_in[4];
    const float* vw  = (const float*)d_in[5];
    const float* vb  = (const float*)d_in[6];
    const float* ow  = (const float*)d_in[7];
    const float* ob  = (const float*)d_in[8];
    float* out = (float*)d_out;

    cudaFuncSetAttribute(attn_kernel,
                         cudaFuncAttributeMaxDynamicSharedMemorySize, ATTN_SMEM);

    dim3 gg(DMODEL/64, M_ROWS/64);          // (12, 128)
    gemm_kernel<0><<<gg, 256>>>(x, qw, qb, nullptr, 0);
    gemm_kernel<0><<<gg, 256>>>(x, kw, kb, nullptr, 1);
    gemm_kernel<0><<<gg, 256>>>(x, vw, vb, nullptr, 2);

    attn_kernel<<<dim3(SEQ/64, BATCH*NHEAD), 256, ATTN_SMEM>>>();

    // A operand resolved inside the kernel (MODE 1) — never pass a
    // __device__ symbol from host code.
    gemm_kernel<1><<<gg, 256>>>(nullptr, ow, ob, out, 0);
}